// round 1
// baseline (speedup 1.0000x reference)
#include <cuda_runtime.h>
#include <cstdint>

#define N_NODES  100000
#define N_EDGES  1600000
#define N_GRAPHS 50
#define FDIM     128

// Scratch: edge aggregations (fits in L2: 2 * 51.2MB) + projected globals (+bias)
__device__ float g_agg[2][(size_t)N_NODES * FDIM];
__device__ float g_gproj[N_GRAPHS * FDIM];

// ---------------------------------------------------------------------------
// Zero the aggregation buffers (float4 grid-stride)
// ---------------------------------------------------------------------------
__global__ void zero_kernel() {
    size_t n = ((size_t)2 * N_NODES * FDIM) / 4;
    float4* p = (float4*)g_agg;
    float4 z = make_float4(0.f, 0.f, 0.f, 0.f);
    for (size_t i = (size_t)blockIdx.x * blockDim.x + threadIdx.x; i < n;
         i += (size_t)gridDim.x * blockDim.x)
        p[i] = z;
}

// ---------------------------------------------------------------------------
// Project globals: g_gproj[g][j] = dot(G[g], Wg[j]) + bias[j]
// ---------------------------------------------------------------------------
__global__ void gproj_kernel(const float* __restrict__ gf,
                             const float* __restrict__ Wg,
                             const float* __restrict__ bias) {
    __shared__ float s[FDIM];
    int g = blockIdx.x, j = threadIdx.x;
    s[j] = gf[g * FDIM + j];
    __syncthreads();
    const float4* wrow = (const float4*)(Wg + (size_t)j * FDIM);
    float acc = 0.f;
#pragma unroll
    for (int k = 0; k < FDIM / 4; k++) {
        float4 w = wrow[k];
        const float4 a = *(const float4*)&s[k * 4];
        acc += a.x * w.x + a.y * w.y + a.z * w.z + a.w * w.w;
    }
    g_gproj[g * FDIM + j] = acc + bias[j];
}

// ---------------------------------------------------------------------------
// Scatter-add edges onto receiver (agg[0]) and sender (agg[1]) nodes.
// One warp per edge; lane l owns float4 cols [4l, 4l+4). red.global.add.v4.f32
// (no return value -> REDG path; destinations are L2-resident).
// ---------------------------------------------------------------------------
__global__ void scatter_kernel(const float4* __restrict__ ef,
                               const int* __restrict__ recv,
                               const int* __restrict__ send) {
    int w = (int)((blockIdx.x * (size_t)blockDim.x + threadIdx.x) >> 5);
    int lane = threadIdx.x & 31;
    if (w >= N_EDGES) return;
    float4 v = __ldg(&ef[(size_t)w * (FDIM / 4) + lane]);
    int r = __ldg(&recv[w]);
    int s = __ldg(&send[w]);
    float* pr = &g_agg[0][(size_t)r * FDIM + lane * 4];
    float* ps = &g_agg[1][(size_t)s * FDIM + lane * 4];
    asm volatile("red.global.add.v4.f32 [%0], {%1,%2,%3,%4};"
                 :: "l"(pr), "f"(v.x), "f"(v.y), "f"(v.z), "f"(v.w) : "memory");
    asm volatile("red.global.add.v4.f32 [%0], {%1,%2,%3,%4};"
                 :: "l"(ps), "f"(v.x), "f"(v.y), "f"(v.z), "f"(v.w) : "memory");
}

// ---------------------------------------------------------------------------
// Fused GEMM: out[m][j] = sum_ph sum_k Asrc[ph][m][k] * Wsrc[ph][j][k]
//                        + g_gproj[gidx[m]][j]          (bias already folded)
// Tiles: 64x64, BK=16, 256 threads, 4x4 register blocking.
// ---------------------------------------------------------------------------
__global__ __launch_bounds__(256) void gemm_kernel(
    const float* __restrict__ node,
    const float* __restrict__ Wn,
    const float* __restrict__ Wi,
    const float* __restrict__ Wo,
    const int* __restrict__ gidx,
    float* __restrict__ out) {
    constexpr int BM = 64, BN = 64, BK = 16;
    __shared__ __align__(16) float As[BK][BM + 4];
    __shared__ __align__(16) float Bs[BK][BN + 4];

    const int m0 = blockIdx.x * BM;
    const int n0 = blockIdx.y * BN;
    const int tid = threadIdx.x;
    const int tx = tid & 15;   // 0..15  -> 4 cols each
    const int ty = tid >> 4;   // 0..15  -> 4 rows each

    const int lm = tid >> 2;          // 0..63 : row within tile for loads
    const int lq = (tid & 3) * 4;     // 0,4,8,12 : k offset for loads

    float acc[4][4] = {};

    const float* Asrc[3] = {node, g_agg[0], g_agg[1]};
    const float* Wsrc[3] = {Wn, Wi, Wo};

    const int arow = m0 + lm;
    const bool arow_ok = (arow < N_NODES);
    const size_t a_off = arow_ok ? (size_t)arow * FDIM : 0;
    const size_t w_off = (size_t)(n0 + lm) * FDIM;

#pragma unroll 1
    for (int ph = 0; ph < 3; ph++) {
        const float4* Arow4 = (const float4*)(Asrc[ph] + a_off);
        const float4* Wrow4 = (const float4*)(Wsrc[ph] + w_off);
#pragma unroll 1
        for (int kc = 0; kc < FDIM; kc += BK) {
            float4 a = __ldg(&Arow4[(kc + lq) >> 2]);
            float4 b = __ldg(&Wrow4[(kc + lq) >> 2]);
            __syncthreads();
            As[lq + 0][lm] = a.x; As[lq + 1][lm] = a.y;
            As[lq + 2][lm] = a.z; As[lq + 3][lm] = a.w;
            Bs[lq + 0][lm] = b.x; Bs[lq + 1][lm] = b.y;
            Bs[lq + 2][lm] = b.z; Bs[lq + 3][lm] = b.w;
            __syncthreads();
#pragma unroll
            for (int k = 0; k < BK; k++) {
                float4 av = *(const float4*)&As[k][ty * 4];
                float4 bv = *(const float4*)&Bs[k][tx * 4];
                acc[0][0] += av.x * bv.x; acc[0][1] += av.x * bv.y;
                acc[0][2] += av.x * bv.z; acc[0][3] += av.x * bv.w;
                acc[1][0] += av.y * bv.x; acc[1][1] += av.y * bv.y;
                acc[1][2] += av.y * bv.z; acc[1][3] += av.y * bv.w;
                acc[2][0] += av.z * bv.x; acc[2][1] += av.z * bv.y;
                acc[2][2] += av.z * bv.z; acc[2][3] += av.z * bv.w;
                acc[3][0] += av.w * bv.x; acc[3][1] += av.w * bv.y;
                acc[3][2] += av.w * bv.z; acc[3][3] += av.w * bv.w;
            }
        }
    }

    // Epilogue: + g_gproj[gidx[row]] (bias folded in), vectorized store.
    const int ncol = n0 + tx * 4;
#pragma unroll
    for (int i = 0; i < 4; i++) {
        int r = m0 + ty * 4 + i;
        if (r < N_NODES) {
            int g = __ldg(&gidx[r]);
            float4 gp = *(const float4*)&g_gproj[(size_t)g * FDIM + ncol];
            float4 o;
            o.x = acc[i][0] + gp.x;
            o.y = acc[i][1] + gp.y;
            o.z = acc[i][2] + gp.z;
            o.w = acc[i][3] + gp.w;
            *(float4*)&out[(size_t)r * FDIM + ncol] = o;
        }
    }
}

// ---------------------------------------------------------------------------
// Launch
// ---------------------------------------------------------------------------
extern "C" void kernel_launch(void* const* d_in, const int* in_sizes, int n_in,
                              void* d_out, int out_size) {
    const float* node_features   = (const float*)d_in[0];
    const float* edge_features   = (const float*)d_in[1];
    const float* global_features = (const float*)d_in[2];
    const float* W_node     = (const float*)d_in[3];
    const float* W_incoming = (const float*)d_in[4];
    const float* W_outgoing = (const float*)d_in[5];
    const float* W_global   = (const float*)d_in[6];
    const float* bias       = (const float*)d_in[7];
    const int*   receivers  = (const int*)d_in[8];
    const int*   senders    = (const int*)d_in[9];
    const int*   graph_idx  = (const int*)d_in[10];
    float* out = (float*)d_out;

    // 1. zero aggregation scratch
    zero_kernel<<<1024, 256>>>();

    // 2. project globals (+bias)
    gproj_kernel<<<N_GRAPHS, FDIM>>>(global_features, W_global, bias);

    // 3. scatter edges (one warp per edge)
    {
        int threads = 256;
        long long total = (long long)N_EDGES * 32;
        int blocks = (int)((total + threads - 1) / threads);
        scatter_kernel<<<blocks, threads>>>((const float4*)edge_features,
                                            receivers, senders);
    }

    // 4. fused 3-term GEMM + global/bias epilogue
    {
        dim3 grid((N_NODES + 63) / 64, FDIM / 64);
        gemm_kernel<<<grid, 256>>>(node_features, W_node, W_incoming,
                                   W_outgoing, graph_idx, out);
    }
}